// round 6
// baseline (speedup 1.0000x reference)
#include <cuda_runtime.h>
#include <cuda_fp16.h>
#include <cstdint>

// Problem constants
#define Bc   16
#define G    8
#define CPER 32
#define CIN  256
#define Jc   64
#define Hc   56
#define Wc   56
#define HW   (Hc * Wc)          // 3136

// Tiling
#define TILE_OR 4               // output rows per block
#define NCOLS   58
#define NREAL   ((TILE_OR + 2) * NCOLS)   // 348 staged spatial rows
#define NPADR   384
#define NSPAT   (TILE_OR * NCOLS)         // 232
#define NTHREADS 256

// smem rows are 80 B (64 B data + 16 B pad): conflict-free for ldmatrix, no XOR swizzle
#define RSTR    80
#define SM_A    0
#define SM_B    (NPADR * RSTR)            // 30720
#define BT_STR  (32 * RSTR)               // 2560 per tap (32 j rows)
#define SMEM_USED (SM_B + 9 * BT_STR)     // 53760
#define SMEM_BYTES (SMEM_USED + 1024)

// epilogue scratch: [32 j][260 floats]
#define OSTR 260

// fp16 weights, prepped once: [g][tap][j][c]
__device__ __half wgt_f16[G * 9 * Jc * CPER];

__device__ __forceinline__ uint32_t smem_u32(const void* p) {
    uint32_t a;
    asm("{ .reg .u64 t; cvta.to.shared.u64 t, %1; cvt.u32.u64 %0, t; }"
        : "=r"(a) : "l"(p));
    return a;
}

#define LDMX4(r0, r1, r2, r3, a) \
    asm volatile("ldmatrix.sync.aligned.m8n8.x4.shared.b16 {%0,%1,%2,%3}, [%4];" \
                 : "=r"(r0), "=r"(r1), "=r"(r2), "=r"(r3) : "r"(a))

#define MMA16816(d, a0, a1, a2, a3, b0, b1) \
    asm volatile("mma.sync.aligned.m16n8k16.row.col.f32.f16.f16.f32 " \
                 "{%0,%1,%2,%3}, {%4,%5,%6,%7}, {%8,%9}, {%0,%1,%2,%3};" \
                 : "+f"((d)[0]), "+f"((d)[1]), "+f"((d)[2]), "+f"((d)[3]) \
                 : "r"(a0), "r"(a1), "r"(a2), "r"(a3), "r"(b0), "r"(b1))

__global__ void __launch_bounds__(256)
prep_weights_kernel(const float* __restrict__ wgt)
{
    int idx = blockIdx.x * 256 + threadIdx.x;
    if (idx >= G * 9 * Jc * CPER) return;
    int c   = idx & 31;
    int j   = (idx >> 5) & 63;
    int tap = (idx >> 11) % 9;
    int g   = idx / (9 * Jc * CPER);
    wgt_f16[idx] = __float2half(wgt[((size_t)(g * Jc + j) * CPER + c) * 9 + tap]);
}

__global__ void __launch_bounds__(NTHREADS, 3)
grouped_conv_hmma_kernel(const float* __restrict__ x,
                         const float* __restrict__ bias,
                         const int*   __restrict__ arr,
                         float*       __restrict__ out)
{
    extern __shared__ char dsm[];
    __shared__ int   ch_s[CPER];
    __shared__ float bias_s[32];

    const int tid  = threadIdx.x;
    const int wid  = tid >> 5;
    const int lane = tid & 31;

    const int g  = blockIdx.x >> 1;
    const int nh = blockIdx.x & 1;          // N-half: j in [nh*32, nh*32+32)
    const int r0 = blockIdx.y * TILE_OR;
    const int b  = blockIdx.z;

    // 1024-align dynamic smem base
    uint32_t raw  = smem_u32(dsm);
    uint32_t base = (raw + 1023u) & ~1023u;
    char* sm = dsm + (base - raw);
    const uint32_t smA = base + SM_A;
    const uint32_t smB = base + SM_B;

    if (tid < CPER) ch_s[tid] = arr[g * CPER + tid];
    if (tid >= 64 && tid < 96) bias_s[tid - 64] = bias[g * Jc + nh * 32 + (tid - 64)];
    __syncthreads();

    // ---- Stage A: gathered input fp16, [n][32ch] rows, stride 80 B
    for (int idx = tid; idx < NPADR * 16; idx += NTHREADS) {
        int cp = idx / NPADR;        // channel pair 0..15
        int n  = idx - cp * NPADR;
        float v0 = 0.0f, v1 = 0.0f;
        if (n < NREAL) {
            int ir = n / NCOLS;
            int ic = n - ir * NCOLS;
            int xr = r0 - 1 + ir;
            int xc = ic - 1;
            if ((unsigned)xr < (unsigned)Hc && (unsigned)xc < (unsigned)Wc) {
                const float* xp = x + (size_t)b * CIN * HW + (size_t)xr * Wc + xc;
                v0 = xp[(size_t)ch_s[2 * cp]     * HW];
                v1 = xp[(size_t)ch_s[2 * cp + 1] * HW];
            }
        }
        *(__half2*)(sm + SM_A + n * RSTR + cp * 4) = __floats2half2_rn(v0, v1);
    }

    // ---- Stage B: 9 taps x 32 j x 64 B from prepped fp16 (coalesced 8-B copies)
    {
        const uint2* wsrc = (const uint2*)wgt_f16;
        for (int idx = tid; idx < 9 * 32 * 8; idx += NTHREADS) {
            int cq  = idx & 7;
            int j   = (idx >> 3) & 31;
            int tap = idx >> 8;
            uint2 v = wsrc[((size_t)(g * 9 + tap) * Jc + nh * 32 + j) * 8 + cq];
            *(uint2*)(sm + SM_B + tap * BT_STR + j * RSTR + cq * 8) = v;
        }
    }
    __syncthreads();

    // ---- MMA mainloop: warp w covers M rows [w*32, w*32+32), N = 32 (this nh)
    const int m0 = wid * 32;
    float d[2][4][4];
#pragma unroll
    for (int mt = 0; mt < 2; ++mt)
#pragma unroll
        for (int nt = 0; nt < 4; ++nt)
#pragma unroll
            for (int k = 0; k < 4; ++k) d[mt][nt][k] = 0.0f;

    const int arow  = (lane & 7) + ((lane >> 3) & 1) * 8;
    const int akoff = (lane >> 4) * 16;
    const int brow  = (lane & 7) + (lane >> 4) * 8;
    const int bkoff = ((lane >> 3) & 1) * 16;

    const uint32_t aBase = smA + (m0 + arow) * RSTR + akoff;
    const uint32_t bBase = smB + brow * RSTR + bkoff;

#pragma unroll
    for (int ky = 0; ky < 3; ++ky) {
#pragma unroll
        for (int kx = 0; kx < 3; ++kx) {
            const int dlt = ky * NCOLS + kx;
            const uint32_t btap = bBase + (ky * 3 + kx) * BT_STR;
#pragma unroll
            for (int ks = 0; ks < 2; ++ks) {
                uint32_t af[2][4];
#pragma unroll
                for (int mt = 0; mt < 2; ++mt)
                    LDMX4(af[mt][0], af[mt][1], af[mt][2], af[mt][3],
                          aBase + (mt * 16 + dlt) * RSTR + ks * 32);
                uint32_t bf[4][2];
#pragma unroll
                for (int np = 0; np < 2; ++np)
                    LDMX4(bf[2 * np][0], bf[2 * np][1], bf[2 * np + 1][0], bf[2 * np + 1][1],
                          btap + np * 16 * RSTR + ks * 32);
#pragma unroll
                for (int mt = 0; mt < 2; ++mt)
#pragma unroll
                    for (int nt = 0; nt < 4; ++nt)
                        MMA16816(d[mt][nt], af[mt][0], af[mt][1], af[mt][2], af[mt][3],
                                 bf[nt][0], bf[nt][1]);
            }
        }
    }

    // ---- Epilogue: transpose through smem, then coalesced global stores
    __syncthreads();
    float* smO = (float*)sm;               // [32 j][OSTR]
#pragma unroll
    for (int mt = 0; mt < 2; ++mt) {
        int row = m0 + mt * 16 + (lane >> 2);
#pragma unroll
        for (int nt = 0; nt < 4; ++nt) {
            int j = nt * 8 + (lane & 3) * 2;
            smO[j * OSTR + row]           = d[mt][nt][0];
            smO[(j + 1) * OSTR + row]     = d[mt][nt][1];
            smO[j * OSTR + row + 8]       = d[mt][nt][2];
            smO[(j + 1) * OSTR + row + 8] = d[mt][nt][3];
        }
    }
    __syncthreads();

    {
        float* obase = out + ((size_t)b * (G * Jc) + g * Jc + nh * 32) * HW
                           + (size_t)r0 * Wc;
        for (int idx = tid; idx < 32 * TILE_OR * Wc; idx += NTHREADS) {
            int j    = idx / (TILE_OR * Wc);
            int r    = idx - j * (TILE_OR * Wc);
            int orow = r / Wc;
            int oc   = r - orow * Wc;
            obase[(size_t)j * HW + orow * Wc + oc] =
                smO[j * OSTR + orow * NCOLS + oc] + bias_s[j];
        }
    }
}

extern "C" void kernel_launch(void* const* d_in, const int* in_sizes, int n_in,
                              void* d_out, int out_size)
{
    const float* x    = (const float*)d_in[0];
    const float* wgt  = (const float*)d_in[1];
    const float* bias = (const float*)d_in[2];
    const int*   arr  = (const int*)d_in[3];
    float* out = (float*)d_out;

    prep_weights_kernel<<<(G * 9 * Jc * CPER + 255) / 256, 256>>>(wgt);

    cudaFuncSetAttribute(grouped_conv_hmma_kernel,
                         cudaFuncAttributeMaxDynamicSharedMemorySize, SMEM_BYTES);

    dim3 grid(G * 2, Hc / TILE_OR, Bc);   // (16, 14, 16) = 3584 blocks
    grouped_conv_hmma_kernel<<<grid, NTHREADS, SMEM_BYTES>>>(x, bias, arr, out);
}